// round 7
// baseline (speedup 1.0000x reference)
#include <cuda_runtime.h>
#include <cuda_fp16.h>
#include <cstdint>

#define NN 50000
#define EE 800000
#define ETOT (EE + NN)
#define DD 128
#define NBSCAN ((NN + 1023) / 1024)

// ---------------- static device scratch ----------------
__device__ float  g_h[NN * DD];
__device__ __half g_xlh[NN * DD];   // xl stored fp16 (attn-only consumer)
__device__ float  g_xr[NN * DD];
__device__ int    g_deg[NN];
__device__ int    g_offs[NN + 1];
__device__ int    g_cur[NN];
__device__ int    g_srcs[ETOT];
__device__ int    g_bsums[NBSCAN];
// pre-split tf32 weights: [layer][k][col 0..255 = Wl|Wr]
__device__ uint32_t g_WH[4 * 128 * 256];
__device__ uint32_t g_WL[4 * 128 * 256];

__device__ __forceinline__ uint32_t f2tf32(float x) {
    uint32_t r;
    asm volatile("cvt.rna.tf32.f32 %0, %1;" : "=r"(r) : "f"(x));
    return r;
}

// ---------------- CSR build ----------------
__global__ void zero_counts() {
    int i = blockIdx.x * blockDim.x + threadIdx.x;
    if (i < NN) { g_deg[i] = 0; g_cur[i] = 0; }
}

__global__ void count_edges(const int* __restrict__ ei) {
    int t = blockIdx.x * blockDim.x + threadIdx.x;
    if (t < ETOT) {
        int dst = (t < EE) ? ei[EE + t] : (t - EE);
        atomicAdd(&g_deg[dst], 1);
    }
}

__global__ void scan_block() {
    __shared__ int sm[256];
    int t = threadIdx.x;
    int base = blockIdx.x * 1024 + t * 4;
    int v0 = (base + 0 < NN) ? g_deg[base + 0] : 0;
    int v1 = (base + 1 < NN) ? g_deg[base + 1] : 0;
    int v2 = (base + 2 < NN) ? g_deg[base + 2] : 0;
    int v3 = (base + 3 < NN) ? g_deg[base + 3] : 0;
    v1 += v0; v2 += v1; v3 += v2;
    sm[t] = v3;
    __syncthreads();
    #pragma unroll
    for (int off = 1; off < 256; off <<= 1) {
        int add = (t >= off) ? sm[t - off] : 0;
        __syncthreads();
        sm[t] += add;
        __syncthreads();
    }
    int prev = (t > 0) ? sm[t - 1] : 0;
    if (base + 0 < NN) g_offs[base + 0] = prev + v0;
    if (base + 1 < NN) g_offs[base + 1] = prev + v1;
    if (base + 2 < NN) g_offs[base + 2] = prev + v2;
    if (base + 3 < NN) g_offs[base + 3] = prev + v3;
    if (t == 255) g_bsums[blockIdx.x] = sm[255];
}

__global__ void scan_spine() {
    if (threadIdx.x == 0) {
        int acc = 0;
        for (int i = 0; i < NBSCAN; i++) { int v = g_bsums[i]; g_bsums[i] = acc; acc += v; }
    }
}

__global__ void scan_fix() {
    int i = blockIdx.x * blockDim.x + threadIdx.x;
    if (i < NN) g_offs[i] = g_offs[i] - g_deg[i] + g_bsums[i >> 10];
    if (i == 0) g_offs[NN] = ETOT;
}

__global__ void fill_edges(const int* __restrict__ ei) {
    int t = blockIdx.x * blockDim.x + threadIdx.x;
    if (t < ETOT) {
        int src, dst;
        if (t < EE) { src = ei[t]; dst = ei[EE + t]; }
        else        { src = t - EE; dst = src; }
        int pos = g_offs[dst] + atomicAdd(&g_cur[dst], 1);
        g_srcs[pos] = src;
    }
}

// ---------------- weight pre-split ----------------
__global__ void split_w(const float* __restrict__ Wl, const float* __restrict__ Wr) {
    int i = blockIdx.x * blockDim.x + threadIdx.x;
    if (i >= 4 * 128 * 256) return;
    int layer = i >> 15;
    int rem = i & 32767;
    int k = rem >> 8;
    int c = rem & 255;
    float v = (c < 128) ? Wl[layer * 16384 + k * 128 + c]
                        : Wr[layer * 16384 + k * 128 + (c - 128)];
    uint32_t hi = f2tf32(v);
    float lo = v - __uint_as_float(hi);
    g_WH[i] = hi;
    g_WL[i] = f2tf32(lo);
}

// ---------------- layer 0 GEMM (K=7) ----------------
__global__ void gemm0(const float* __restrict__ x,
                      const float* __restrict__ Wl0, const float* __restrict__ Wr0,
                      const float* __restrict__ bl0, const float* __restrict__ br0) {
    int node = blockIdx.x;
    int j = threadIdx.x;
    __shared__ float xs[7];
    if (j < 7) xs[j] = x[node * 7 + j];
    __syncthreads();
    const float* W = (j < 128) ? Wl0 : Wr0;
    int c = j & 127;
    float acc = (j < 128) ? bl0[c] : br0[c];
    #pragma unroll
    for (int k = 0; k < 7; k++) acc += xs[k] * W[k * 128 + c];
    if (j < 128) g_xlh[node * DD + c] = __float2half_rn(acc);
    else         g_xr[node * DD + c] = acc;
}

// ---------------- TC GEMM: double-buffered, cp.async B, A=tf32, B=hi/lo ----------------
#define KC 16
#define STAGE_WORDS 6912
#define OFF_BH 2560
#define OFF_BL 4736
#define GEMM_SMEM_BYTES (2 * STAGE_WORDS * 4)

__device__ __forceinline__ void mma_tf32(float c[4], const uint32_t a[4], uint32_t b0, uint32_t b1) {
    asm volatile(
        "mma.sync.aligned.m16n8k8.row.col.f32.tf32.tf32.f32 "
        "{%0,%1,%2,%3}, {%4,%5,%6,%7}, {%8,%9}, {%0,%1,%2,%3};"
        : "+f"(c[0]), "+f"(c[1]), "+f"(c[2]), "+f"(c[3])
        : "r"(a[0]), "r"(a[1]), "r"(a[2]), "r"(a[3]), "r"(b0), "r"(b1));
}

__device__ __forceinline__ void cp16(uint32_t* dst_smem, const uint32_t* src_gmem) {
    uint32_t saddr = (uint32_t)__cvta_generic_to_shared(dst_smem);
    asm volatile("cp.async.cg.shared.global [%0], [%1], 16;" :: "r"(saddr), "l"(src_gmem));
}

__global__ __launch_bounds__(256, 2) void gemm_tc(int layer,
                                                  const float* __restrict__ bl_,
                                                  const float* __restrict__ br_) {
    extern __shared__ uint32_t smem[];

    int tid  = threadIdx.x;
    int lane = tid & 31;
    int wid  = tid >> 5;
    int g    = lane >> 2;
    int tig  = lane & 3;
    int wm   = wid >> 1;
    int wn   = wid & 1;
    int m_base = wm * 32;
    int n_base = wn * 64;
    int row0 = blockIdx.x * 128;
    int yhalf = blockIdx.y;

    const uint32_t* WHbase = g_WH + layer * 32768 + yhalf * 128;
    const uint32_t* WLbase = g_WL + layer * 32768 + yhalf * 128;

    float c[2][8][4];
    #pragma unroll
    for (int mi = 0; mi < 2; mi++)
        #pragma unroll
        for (int ni = 0; ni < 8; ni++)
            #pragma unroll
            for (int q = 0; q < 4; q++) c[mi][ni][q] = 0.f;

    int ar  = tid >> 1;
    int akq = (tid & 1) * 8;
    int bk  = tid >> 4;
    int bc  = (tid & 15) * 8;
    int arow = row0 + ar;
    bool a_ok = (arow < NN);
    const float* a_gp = &g_h[(size_t)arow * DD + akq];

    float4 fa0 = make_float4(0.f, 0.f, 0.f, 0.f);
    float4 fa1 = make_float4(0.f, 0.f, 0.f, 0.f);
    if (a_ok) {
        fa0 = *(const float4*)&a_gp[0];
        fa1 = *(const float4*)&a_gp[4];
    }
    {
        uint32_t* BH = smem + OFF_BH;
        uint32_t* BL = smem + OFF_BL;
        const uint32_t* sH = WHbase + bk * 256 + bc;
        const uint32_t* sL = WLbase + bk * 256 + bc;
        cp16(&BH[bk * 136 + bc],     &sH[0]);
        cp16(&BH[bk * 136 + bc + 4], &sH[4]);
        cp16(&BL[bk * 136 + bc],     &sL[0]);
        cp16(&BL[bk * 136 + bc + 4], &sL[4]);
        asm volatile("cp.async.commit_group;");
    }

    for (int it = 0; it < 8; it++) {
        int cur = it & 1;
        uint32_t* As  = smem + cur * STAGE_WORDS;
        uint32_t* BsH = As + OFF_BH;
        uint32_t* BsL = As + OFF_BL;

        {
            float f[8] = {fmaxf(fa0.x, 0.f), fmaxf(fa0.y, 0.f), fmaxf(fa0.z, 0.f), fmaxf(fa0.w, 0.f),
                          fmaxf(fa1.x, 0.f), fmaxf(fa1.y, 0.f), fmaxf(fa1.z, 0.f), fmaxf(fa1.w, 0.f)};
            #pragma unroll
            for (int j = 0; j < 8; j++) As[ar * 20 + akq + j] = f2tf32(f[j]);
        }
        asm volatile("cp.async.wait_group 0;");
        __syncthreads();
        if (it < 7) {
            int k0n = (it + 1) * KC;
            if (a_ok) {
                fa0 = *(const float4*)&a_gp[k0n];
                fa1 = *(const float4*)&a_gp[k0n + 4];
            }
            uint32_t* An  = smem + ((it + 1) & 1) * STAGE_WORDS;
            uint32_t* BHn = An + OFF_BH;
            uint32_t* BLn = An + OFF_BL;
            const uint32_t* sH = WHbase + (k0n + bk) * 256 + bc;
            const uint32_t* sL = WLbase + (k0n + bk) * 256 + bc;
            cp16(&BHn[bk * 136 + bc],     &sH[0]);
            cp16(&BHn[bk * 136 + bc + 4], &sH[4]);
            cp16(&BLn[bk * 136 + bc],     &sL[0]);
            cp16(&BLn[bk * 136 + bc + 4], &sL[4]);
            asm volatile("cp.async.commit_group;");
        }

        #pragma unroll
        for (int ks = 0; ks < KC; ks += 8) {
            uint32_t a[2][4];
            #pragma unroll
            for (int mi = 0; mi < 2; mi++) {
                int r = m_base + mi * 16 + g;
                a[mi][0] = As[r * 20 + ks + tig];
                a[mi][1] = As[(r + 8) * 20 + ks + tig];
                a[mi][2] = As[r * 20 + ks + tig + 4];
                a[mi][3] = As[(r + 8) * 20 + ks + tig + 4];
            }
            #pragma unroll
            for (int ni = 0; ni < 8; ni++) {
                int cc = n_base + ni * 8 + g;
                uint32_t bH0 = BsH[(ks + tig) * 136 + cc],     bL0 = BsL[(ks + tig) * 136 + cc];
                uint32_t bH1 = BsH[(ks + tig + 4) * 136 + cc], bL1 = BsL[(ks + tig + 4) * 136 + cc];
                #pragma unroll
                for (int mi = 0; mi < 2; mi++) {
                    mma_tf32(c[mi][ni], a[mi], bH0, bH1);
                    mma_tf32(c[mi][ni], a[mi], bL0, bL1);
                }
            }
        }
        __syncthreads();
    }

    // --- epilogue: xl -> fp16, xr -> fp32 ---
    if (yhalf == 0) {
        #pragma unroll
        for (int ni = 0; ni < 8; ni++) {
            int cn = n_base + ni * 8 + tig * 2;
            float b0 = bl_[cn], b1 = bl_[cn + 1];
            #pragma unroll
            for (int mi = 0; mi < 2; mi++) {
                int ra = row0 + m_base + mi * 16 + g;
                int rb = ra + 8;
                if (ra < NN)
                    *(__half2*)&g_xlh[(size_t)ra * DD + cn] =
                        __floats2half2_rn(c[mi][ni][0] + b0, c[mi][ni][1] + b1);
                if (rb < NN)
                    *(__half2*)&g_xlh[(size_t)rb * DD + cn] =
                        __floats2half2_rn(c[mi][ni][2] + b0, c[mi][ni][3] + b1);
            }
        }
    } else {
        #pragma unroll
        for (int ni = 0; ni < 8; ni++) {
            int cn = n_base + ni * 8 + tig * 2;
            float b0 = br_[cn], b1 = br_[cn + 1];
            #pragma unroll
            for (int mi = 0; mi < 2; mi++) {
                int ra = row0 + m_base + mi * 16 + g;
                int rb = ra + 8;
                if (ra < NN)
                    *(float2*)&g_xr[(size_t)ra * DD + cn] =
                        make_float2(c[mi][ni][0] + b0, c[mi][ni][1] + b1);
                if (rb < NN)
                    *(float2*)&g_xr[(size_t)rb * DD + cn] =
                        make_float2(c[mi][ni][2] + b0, c[mi][ni][3] + b1);
            }
        }
    }
}

// ---------------- attention: warp per node, fp16 xl gather, fp32 math ----------------
__global__ void attn(const float* __restrict__ avec, const float* __restrict__ bvec,
                     float* __restrict__ outp) {
    const unsigned FULL = 0xffffffffu;
    int w = (blockIdx.x * blockDim.x + threadIdx.x) >> 5;
    if (w >= NN) return;
    int lane = threadIdx.x & 31;

    float4 xr4 = *(float4*)&g_xr[(size_t)w * DD + lane * 4];
    float4 a4  = *(const float4*)&avec[lane * 4];

    int p = g_offs[w], end = g_offs[w + 1];
    float m = -1e30f, s = 0.f;
    float ax = 0.f, ay = 0.f, az = 0.f, aw = 0.f;

    int src = g_srcs[p];
    uint2 raw = *(const uint2*)&g_xlh[(size_t)src * DD + lane * 4];

    while (p < end) {
        uint2 rc = raw;
        int pn = p + 1;
        if (pn < end) {
            int s2 = g_srcs[pn];
            raw = *(const uint2*)&g_xlh[(size_t)s2 * DD + lane * 4];
        }
        float2 f0 = __half22float2(*reinterpret_cast<const __half2*>(&rc.x));
        float2 f1 = __half22float2(*reinterpret_cast<const __half2*>(&rc.y));
        float cx = f0.x, cy = f0.y, cz = f1.x, cw = f1.y;

        float vx = cx + xr4.x; vx = (vx > 0.f) ? vx : 0.2f * vx;
        float vy = cy + xr4.y; vy = (vy > 0.f) ? vy : 0.2f * vy;
        float vz = cz + xr4.z; vz = (vz > 0.f) ? vz : 0.2f * vz;
        float vw = cw + xr4.w; vw = (vw > 0.f) ? vw : 0.2f * vw;
        float d = vx * a4.x + vy * a4.y + vz * a4.z + vw * a4.w;
        d += __shfl_xor_sync(FULL, d, 16);
        d += __shfl_xor_sync(FULL, d, 8);
        d += __shfl_xor_sync(FULL, d, 4);
        d += __shfl_xor_sync(FULL, d, 2);
        d += __shfl_xor_sync(FULL, d, 1);

        float mn  = fmaxf(m, d);
        float sc  = __expf(m - mn);
        float wgt = __expf(d - mn);
        s  = s * sc + wgt;
        ax = ax * sc + wgt * cx;
        ay = ay * sc + wgt * cy;
        az = az * sc + wgt * cz;
        aw = aw * sc + wgt * cw;
        m = mn;
        p = pn;
    }

    float inv = 1.f / s;
    float4 b4 = *(const float4*)&bvec[lane * 4];
    float* o = outp ? outp : g_h;
    float4 r = make_float4(ax * inv + b4.x, ay * inv + b4.y,
                           az * inv + b4.z, aw * inv + b4.w);
    *(float4*)&o[(size_t)w * DD + lane * 4] = r;
}

// ---------------- launch ----------------
extern "C" void kernel_launch(void* const* d_in, const int* in_sizes, int n_in,
                              void* d_out, int out_size) {
    const float* x    = (const float*)d_in[0];
    const int*   ei   = (const int*)d_in[1];
    const float* Wl0  = (const float*)d_in[2];
    const float* Wr0  = (const float*)d_in[3];
    const float* bl0  = (const float*)d_in[4];
    const float* br0  = (const float*)d_in[5];
    const float* Wl   = (const float*)d_in[6];
    const float* Wr   = (const float*)d_in[7];
    const float* bl   = (const float*)d_in[8];
    const float* br   = (const float*)d_in[9];
    const float* att  = (const float*)d_in[10];
    const float* bias = (const float*)d_in[11];
    float* out = (float*)d_out;

    cudaFuncSetAttribute(gemm_tc, cudaFuncAttributeMaxDynamicSharedMemorySize, GEMM_SMEM_BYTES);

    zero_counts<<<(NN + 255) / 256, 256>>>();
    count_edges<<<(ETOT + 255) / 256, 256>>>(ei);
    scan_block<<<NBSCAN, 256>>>();
    scan_spine<<<1, 32>>>();
    scan_fix<<<(NN + 255) / 256, 256>>>();
    fill_edges<<<(ETOT + 255) / 256, 256>>>(ei);
    split_w<<<(4 * 128 * 256 + 255) / 256, 256>>>(Wl, Wr);

    const int attn_blocks = (NN * 32 + 255) / 256;
    dim3 tc_grid((NN + 127) / 128, 2);

    gemm0<<<NN, 256>>>(x, Wl0, Wr0, bl0, br0);
    attn<<<attn_blocks, 256>>>(att, bias, nullptr);

    for (int t = 1; t < 5; t++) {
        gemm_tc<<<tc_grid, 256, GEMM_SMEM_BYTES>>>(t - 1, bl + (size_t)(t - 1) * 128,
                                                   br + (size_t)(t - 1) * 128);
        attn<<<attn_blocks, 256>>>(att + (size_t)t * 128, bias + (size_t)t * 128,
                                   (t == 4) ? out : nullptr);
    }
}

// round 8
// speedup vs baseline: 1.1945x; 1.1945x over previous
#include <cuda_runtime.h>
#include <cstdint>

#define NN 50000
#define EE 800000
#define ETOT (EE + NN)
#define DD 128
#define NBSCAN ((NN + 1023) / 1024)

// ---------------- static device scratch ----------------
__device__ float g_h[NN * DD];
__device__ float g_xl[NN * DD];
__device__ float g_xr[NN * DD];
__device__ int   g_deg[NN];
__device__ int   g_offs[NN + 1];
__device__ int   g_cur[NN];
__device__ int   g_srcs[ETOT];
__device__ int   g_bsums[NBSCAN];
// pre-split tf32 weights: [layer][k][col 0..255 = Wl|Wr]
__device__ uint32_t g_WH[4 * 128 * 256];
__device__ uint32_t g_WL[4 * 128 * 256];

__device__ __forceinline__ uint32_t f2tf32(float x) {
    uint32_t r;
    asm volatile("cvt.rna.tf32.f32 %0, %1;" : "=r"(r) : "f"(x));
    return r;
}

// ---------------- CSR build ----------------
__global__ void zero_counts() {
    int i = blockIdx.x * blockDim.x + threadIdx.x;
    if (i < NN) { g_deg[i] = 0; g_cur[i] = 0; }
}

__global__ void count_edges(const int* __restrict__ ei) {
    int t = blockIdx.x * blockDim.x + threadIdx.x;
    if (t < ETOT) {
        int dst = (t < EE) ? ei[EE + t] : (t - EE);
        atomicAdd(&g_deg[dst], 1);
    }
}

__global__ void scan_block() {
    __shared__ int sm[256];
    int t = threadIdx.x;
    int base = blockIdx.x * 1024 + t * 4;
    int v0 = (base + 0 < NN) ? g_deg[base + 0] : 0;
    int v1 = (base + 1 < NN) ? g_deg[base + 1] : 0;
    int v2 = (base + 2 < NN) ? g_deg[base + 2] : 0;
    int v3 = (base + 3 < NN) ? g_deg[base + 3] : 0;
    v1 += v0; v2 += v1; v3 += v2;
    sm[t] = v3;
    __syncthreads();
    #pragma unroll
    for (int off = 1; off < 256; off <<= 1) {
        int add = (t >= off) ? sm[t - off] : 0;
        __syncthreads();
        sm[t] += add;
        __syncthreads();
    }
    int prev = (t > 0) ? sm[t - 1] : 0;
    if (base + 0 < NN) g_offs[base + 0] = prev + v0;
    if (base + 1 < NN) g_offs[base + 1] = prev + v1;
    if (base + 2 < NN) g_offs[base + 2] = prev + v2;
    if (base + 3 < NN) g_offs[base + 3] = prev + v3;
    if (t == 255) g_bsums[blockIdx.x] = sm[255];
}

__global__ void scan_spine() {
    if (threadIdx.x == 0) {
        int acc = 0;
        for (int i = 0; i < NBSCAN; i++) { int v = g_bsums[i]; g_bsums[i] = acc; acc += v; }
    }
}

__global__ void scan_fix() {
    int i = blockIdx.x * blockDim.x + threadIdx.x;
    if (i < NN) g_offs[i] = g_offs[i] - g_deg[i] + g_bsums[i >> 10];
    if (i == 0) g_offs[NN] = ETOT;
}

__global__ void fill_edges(const int* __restrict__ ei) {
    int t = blockIdx.x * blockDim.x + threadIdx.x;
    if (t < ETOT) {
        int src, dst;
        if (t < EE) { src = ei[t]; dst = ei[EE + t]; }
        else        { src = t - EE; dst = src; }
        int pos = g_offs[dst] + atomicAdd(&g_cur[dst], 1);
        g_srcs[pos] = src;
    }
}

// ---------------- weight pre-split ----------------
__global__ void split_w(const float* __restrict__ Wl, const float* __restrict__ Wr) {
    int i = blockIdx.x * blockDim.x + threadIdx.x;
    if (i >= 4 * 128 * 256) return;
    int layer = i >> 15;
    int rem = i & 32767;
    int k = rem >> 8;
    int c = rem & 255;
    float v = (c < 128) ? Wl[layer * 16384 + k * 128 + c]
                        : Wr[layer * 16384 + k * 128 + (c - 128)];
    uint32_t hi = f2tf32(v);
    float lo = v - __uint_as_float(hi);
    g_WH[i] = hi;
    g_WL[i] = f2tf32(lo);
}

// ---------------- layer 0 GEMM (K=7) ----------------
__global__ void gemm0(const float* __restrict__ x,
                      const float* __restrict__ Wl0, const float* __restrict__ Wr0,
                      const float* __restrict__ bl0, const float* __restrict__ br0) {
    int node = blockIdx.x;
    int j = threadIdx.x;
    __shared__ float xs[7];
    if (j < 7) xs[j] = x[node * 7 + j];
    __syncthreads();
    const float* W = (j < 128) ? Wl0 : Wr0;
    int c = j & 127;
    float acc = (j < 128) ? bl0[c] : br0[c];
    #pragma unroll
    for (int k = 0; k < 7; k++) acc += xs[k] * W[k * 128 + c];
    if (j < 128) g_xl[node * DD + c] = acc;
    else         g_xr[node * DD + c] = acc;
}

// ---------------- TC GEMM: double-buffered, cp.async B, A=tf32, B=hi/lo ----------------
#define KC 16
#define STAGE_WORDS 6912
#define OFF_BH 2560
#define OFF_BL 4736
#define GEMM_SMEM_BYTES (2 * STAGE_WORDS * 4)

__device__ __forceinline__ void mma_tf32(float c[4], const uint32_t a[4], uint32_t b0, uint32_t b1) {
    asm volatile(
        "mma.sync.aligned.m16n8k8.row.col.f32.tf32.tf32.f32 "
        "{%0,%1,%2,%3}, {%4,%5,%6,%7}, {%8,%9}, {%0,%1,%2,%3};"
        : "+f"(c[0]), "+f"(c[1]), "+f"(c[2]), "+f"(c[3])
        : "r"(a[0]), "r"(a[1]), "r"(a[2]), "r"(a[3]), "r"(b0), "r"(b1));
}

__device__ __forceinline__ void cp16(uint32_t* dst_smem, const uint32_t* src_gmem) {
    uint32_t saddr = (uint32_t)__cvta_generic_to_shared(dst_smem);
    asm volatile("cp.async.cg.shared.global [%0], [%1], 16;" :: "r"(saddr), "l"(src_gmem));
}

__global__ __launch_bounds__(256, 2) void gemm_tc(int layer,
                                                  const float* __restrict__ bl_,
                                                  const float* __restrict__ br_) {
    extern __shared__ uint32_t smem[];

    int tid  = threadIdx.x;
    int lane = tid & 31;
    int wid  = tid >> 5;
    int g    = lane >> 2;
    int tig  = lane & 3;
    int wm   = wid >> 1;
    int wn   = wid & 1;
    int m_base = wm * 32;
    int n_base = wn * 64;
    int row0 = blockIdx.x * 128;
    int yhalf = blockIdx.y;

    const uint32_t* WHbase = g_WH + layer * 32768 + yhalf * 128;
    const uint32_t* WLbase = g_WL + layer * 32768 + yhalf * 128;

    float c[2][8][4];
    #pragma unroll
    for (int mi = 0; mi < 2; mi++)
        #pragma unroll
        for (int ni = 0; ni < 8; ni++)
            #pragma unroll
            for (int q = 0; q < 4; q++) c[mi][ni][q] = 0.f;

    int ar  = tid >> 1;
    int akq = (tid & 1) * 8;
    int bk  = tid >> 4;
    int bc  = (tid & 15) * 8;
    int arow = row0 + ar;
    bool a_ok = (arow < NN);
    const float* a_gp = &g_h[(size_t)arow * DD + akq];

    float4 fa0 = make_float4(0.f, 0.f, 0.f, 0.f);
    float4 fa1 = make_float4(0.f, 0.f, 0.f, 0.f);
    if (a_ok) {
        fa0 = *(const float4*)&a_gp[0];
        fa1 = *(const float4*)&a_gp[4];
    }
    {
        uint32_t* BH = smem + OFF_BH;
        uint32_t* BL = smem + OFF_BL;
        const uint32_t* sH = WHbase + bk * 256 + bc;
        const uint32_t* sL = WLbase + bk * 256 + bc;
        cp16(&BH[bk * 136 + bc],     &sH[0]);
        cp16(&BH[bk * 136 + bc + 4], &sH[4]);
        cp16(&BL[bk * 136 + bc],     &sL[0]);
        cp16(&BL[bk * 136 + bc + 4], &sL[4]);
        asm volatile("cp.async.commit_group;");
    }

    for (int it = 0; it < 8; it++) {
        int cur = it & 1;
        uint32_t* As  = smem + cur * STAGE_WORDS;
        uint32_t* BsH = As + OFF_BH;
        uint32_t* BsL = As + OFF_BL;

        {
            float f[8] = {fmaxf(fa0.x, 0.f), fmaxf(fa0.y, 0.f), fmaxf(fa0.z, 0.f), fmaxf(fa0.w, 0.f),
                          fmaxf(fa1.x, 0.f), fmaxf(fa1.y, 0.f), fmaxf(fa1.z, 0.f), fmaxf(fa1.w, 0.f)};
            #pragma unroll
            for (int j = 0; j < 8; j++) As[ar * 20 + akq + j] = f2tf32(f[j]);
        }
        asm volatile("cp.async.wait_group 0;");
        __syncthreads();
        if (it < 7) {
            int k0n = (it + 1) * KC;
            if (a_ok) {
                fa0 = *(const float4*)&a_gp[k0n];
                fa1 = *(const float4*)&a_gp[k0n + 4];
            }
            uint32_t* An  = smem + ((it + 1) & 1) * STAGE_WORDS;
            uint32_t* BHn = An + OFF_BH;
            uint32_t* BLn = An + OFF_BL;
            const uint32_t* sH = WHbase + (k0n + bk) * 256 + bc;
            const uint32_t* sL = WLbase + (k0n + bk) * 256 + bc;
            cp16(&BHn[bk * 136 + bc],     &sH[0]);
            cp16(&BHn[bk * 136 + bc + 4], &sH[4]);
            cp16(&BLn[bk * 136 + bc],     &sL[0]);
            cp16(&BLn[bk * 136 + bc + 4], &sL[4]);
            asm volatile("cp.async.commit_group;");
        }

        #pragma unroll
        for (int ks = 0; ks < KC; ks += 8) {
            uint32_t a[2][4];
            #pragma unroll
            for (int mi = 0; mi < 2; mi++) {
                int r = m_base + mi * 16 + g;
                a[mi][0] = As[r * 20 + ks + tig];
                a[mi][1] = As[(r + 8) * 20 + ks + tig];
                a[mi][2] = As[r * 20 + ks + tig + 4];
                a[mi][3] = As[(r + 8) * 20 + ks + tig + 4];
            }
            #pragma unroll
            for (int ni = 0; ni < 8; ni++) {
                int cc = n_base + ni * 8 + g;
                uint32_t bH0 = BsH[(ks + tig) * 136 + cc],     bL0 = BsL[(ks + tig) * 136 + cc];
                uint32_t bH1 = BsH[(ks + tig + 4) * 136 + cc], bL1 = BsL[(ks + tig + 4) * 136 + cc];
                #pragma unroll
                for (int mi = 0; mi < 2; mi++) {
                    mma_tf32(c[mi][ni], a[mi], bH0, bH1);
                    mma_tf32(c[mi][ni], a[mi], bL0, bL1);
                }
            }
        }
        __syncthreads();
    }

    // --- epilogue ---
    const float* bias = yhalf ? br_ : bl_;
    float* dst = yhalf ? g_xr : g_xl;
    #pragma unroll
    for (int ni = 0; ni < 8; ni++) {
        int cn = n_base + ni * 8 + tig * 2;
        float b0 = bias[cn], b1 = bias[cn + 1];
        #pragma unroll
        for (int mi = 0; mi < 2; mi++) {
            int ra = row0 + m_base + mi * 16 + g;
            int rb = ra + 8;
            if (ra < NN)
                *(float2*)&dst[ra * DD + cn] = make_float2(c[mi][ni][0] + b0, c[mi][ni][1] + b1);
            if (rb < NN)
                *(float2*)&dst[rb * DD + cn] = make_float2(c[mi][ni][2] + b0, c[mi][ni][3] + b1);
        }
    }
}

// ---------------- attention v3: warp per node, no-max softmax, ILP-4 ----------------
__device__ __forceinline__ float dleaky(float4 c, float4 xr, float4 a, float d) {
    float v;
    v = c.x + xr.x; v = (v > 0.f) ? v : 0.2f * v; d = fmaf(v, a.x, d);
    v = c.y + xr.y; v = (v > 0.f) ? v : 0.2f * v; d = fmaf(v, a.y, d);
    v = c.z + xr.z; v = (v > 0.f) ? v : 0.2f * v; d = fmaf(v, a.z, d);
    v = c.w + xr.w; v = (v > 0.f) ? v : 0.2f * v; d = fmaf(v, a.w, d);
    return d;
}

__global__ void attn(const float* __restrict__ avec, const float* __restrict__ bvec,
                     float* __restrict__ outp) {
    const unsigned FULL = 0xffffffffu;
    int w = (blockIdx.x * blockDim.x + threadIdx.x) >> 5;
    if (w >= NN) return;
    int lane = threadIdx.x & 31;

    float4 xr4 = *(float4*)&g_xr[(size_t)w * DD + lane * 4];
    float4 a4  = *(const float4*)&avec[lane * 4];

    int p = g_offs[w], end = g_offs[w + 1];
    float s = 0.f;
    float ax = 0.f, ay = 0.f, az = 0.f, aw = 0.f;

    // ILP-4 main loop: 4 independent edges per iteration
    while (p + 4 <= end) {
        int s0 = g_srcs[p], s1 = g_srcs[p + 1], s2 = g_srcs[p + 2], s3 = g_srcs[p + 3];
        float4 c0 = *(const float4*)&g_xl[(size_t)s0 * DD + lane * 4];
        float4 c1 = *(const float4*)&g_xl[(size_t)s1 * DD + lane * 4];
        float4 c2 = *(const float4*)&g_xl[(size_t)s2 * DD + lane * 4];
        float4 c3 = *(const float4*)&g_xl[(size_t)s3 * DD + lane * 4];

        float d0 = dleaky(c0, xr4, a4, 0.f);
        float d1 = dleaky(c1, xr4, a4, 0.f);
        float d2 = dleaky(c2, xr4, a4, 0.f);
        float d3 = dleaky(c3, xr4, a4, 0.f);

        #pragma unroll
        for (int off = 16; off >= 1; off >>= 1) {
            d0 += __shfl_xor_sync(FULL, d0, off);
            d1 += __shfl_xor_sync(FULL, d1, off);
            d2 += __shfl_xor_sync(FULL, d2, off);
            d3 += __shfl_xor_sync(FULL, d3, off);
        }

        float w0 = __expf(d0), w1 = __expf(d1), w2 = __expf(d2), w3 = __expf(d3);
        s += (w0 + w1) + (w2 + w3);
        ax += w0 * c0.x + w1 * c1.x + w2 * c2.x + w3 * c3.x;
        ay += w0 * c0.y + w1 * c1.y + w2 * c2.y + w3 * c3.y;
        az += w0 * c0.z + w1 * c1.z + w2 * c2.z + w3 * c3.z;
        aw += w0 * c0.w + w1 * c1.w + w2 * c2.w + w3 * c3.w;
        p += 4;
    }

    // remainder
    while (p < end) {
        int s0 = g_srcs[p];
        float4 c0 = *(const float4*)&g_xl[(size_t)s0 * DD + lane * 4];
        float d0 = dleaky(c0, xr4, a4, 0.f);
        #pragma unroll
        for (int off = 16; off >= 1; off >>= 1)
            d0 += __shfl_xor_sync(FULL, d0, off);
        float w0 = __expf(d0);
        s += w0;
        ax += w0 * c0.x;
        ay += w0 * c0.y;
        az += w0 * c0.z;
        aw += w0 * c0.w;
        p++;
    }

    float inv = 1.f / s;
    float4 b4 = *(const float4*)&bvec[lane * 4];
    float* o = outp ? outp : g_h;
    float4 r = make_float4(ax * inv + b4.x, ay * inv + b4.y,
                           az * inv + b4.z, aw * inv + b4.w);
    *(float4*)&o[(size_t)w * DD + lane * 4] = r;
}

// ---------------- launch ----------------
extern "C" void kernel_launch(void* const* d_in, const int* in_sizes, int n_in,
                              void* d_out, int out_size) {
    const float* x    = (const float*)d_in[0];
    const int*   ei   = (const int*)d_in[1];
    const float* Wl0  = (const float*)d_in[2];
    const float* Wr0  = (const float*)d_in[3];
    const float* bl0  = (const float*)d_in[4];
    const float* br0  = (const float*)d_in[5];
    const float* Wl   = (const float*)d_in[6];
    const float* Wr   = (const float*)d_in[7];
    const float* bl   = (const float*)d_in[8];
    const float* br   = (const float*)d_in[9];
    const float* att  = (const float*)d_in[10];
    const float* bias = (const float*)d_in[11];
    float* out = (float*)d_out;

    cudaFuncSetAttribute(gemm_tc, cudaFuncAttributeMaxDynamicSharedMemorySize, GEMM_SMEM_BYTES);

    zero_counts<<<(NN + 255) / 256, 256>>>();
    count_edges<<<(ETOT + 255) / 256, 256>>>(ei);
    scan_block<<<NBSCAN, 256>>>();
    scan_spine<<<1, 32>>>();
    scan_fix<<<(NN + 255) / 256, 256>>>();
    fill_edges<<<(ETOT + 255) / 256, 256>>>(ei);
    split_w<<<(4 * 128 * 256 + 255) / 256, 256>>>(Wl, Wr);

    const int attn_blocks = (NN * 32 + 255) / 256;
    dim3 tc_grid((NN + 127) / 128, 2);

    gemm0<<<NN, 256>>>(x, Wl0, Wr0, bl0, br0);
    attn<<<attn_blocks, 256>>>(att, bias, nullptr);

    for (int t = 1; t < 5; t++) {
        gemm_tc<<<tc_grid, 256, GEMM_SMEM_BYTES>>>(t - 1, bl + (size_t)(t - 1) * 128,
                                                   br + (size_t)(t - 1) * 128);
        attn<<<attn_blocks, 256>>>(att + (size_t)t * 128, bias + (size_t)t * 128,
                                   (t == 4) ? out : nullptr);
    }
}

// round 9
// speedup vs baseline: 1.2390x; 1.0373x over previous
#include <cuda_runtime.h>
#include <cstdint>

#define NN 50000
#define EE 800000
#define ETOT (EE + NN)
#define DD 128
#define NBSCAN ((NN + 1023) / 1024)

// ---------------- static device scratch ----------------
__device__ float g_h[NN * DD];
__device__ float g_xl[NN * DD];
__device__ float g_xr[NN * DD];
__device__ int   g_deg[NN];
__device__ int   g_offs[NN + 1];
__device__ int   g_cur[NN];
__device__ int   g_srcs[ETOT];
__device__ int   g_bsums[NBSCAN];
// pre-converted tf32 weights: [layer][k][col 0..255 = Wl|Wr]
__device__ uint32_t g_WH[4 * 128 * 256];

__device__ __forceinline__ uint32_t f2tf32(float x) {
    uint32_t r;
    asm volatile("cvt.rna.tf32.f32 %0, %1;" : "=r"(r) : "f"(x));
    return r;
}

// ---------------- CSR build ----------------
__global__ void zero_counts() {
    int i = blockIdx.x * blockDim.x + threadIdx.x;
    if (i < NN) { g_deg[i] = 0; g_cur[i] = 0; }
}

__global__ void count_edges(const int* __restrict__ ei) {
    int t = blockIdx.x * blockDim.x + threadIdx.x;
    if (t < ETOT) {
        int dst = (t < EE) ? ei[EE + t] : (t - EE);
        atomicAdd(&g_deg[dst], 1);
    }
}

__global__ void scan_block() {
    __shared__ int sm[256];
    int t = threadIdx.x;
    int base = blockIdx.x * 1024 + t * 4;
    int v0 = (base + 0 < NN) ? g_deg[base + 0] : 0;
    int v1 = (base + 1 < NN) ? g_deg[base + 1] : 0;
    int v2 = (base + 2 < NN) ? g_deg[base + 2] : 0;
    int v3 = (base + 3 < NN) ? g_deg[base + 3] : 0;
    v1 += v0; v2 += v1; v3 += v2;
    sm[t] = v3;
    __syncthreads();
    #pragma unroll
    for (int off = 1; off < 256; off <<= 1) {
        int add = (t >= off) ? sm[t - off] : 0;
        __syncthreads();
        sm[t] += add;
        __syncthreads();
    }
    int prev = (t > 0) ? sm[t - 1] : 0;
    if (base + 0 < NN) g_offs[base + 0] = prev + v0;
    if (base + 1 < NN) g_offs[base + 1] = prev + v1;
    if (base + 2 < NN) g_offs[base + 2] = prev + v2;
    if (base + 3 < NN) g_offs[base + 3] = prev + v3;
    if (t == 255) g_bsums[blockIdx.x] = sm[255];
}

__global__ void scan_spine() {
    if (threadIdx.x == 0) {
        int acc = 0;
        for (int i = 0; i < NBSCAN; i++) { int v = g_bsums[i]; g_bsums[i] = acc; acc += v; }
    }
}

__global__ void scan_fix() {
    int i = blockIdx.x * blockDim.x + threadIdx.x;
    if (i < NN) g_offs[i] = g_offs[i] - g_deg[i] + g_bsums[i >> 10];
    if (i == 0) g_offs[NN] = ETOT;
}

__global__ void fill_edges(const int* __restrict__ ei) {
    int t = blockIdx.x * blockDim.x + threadIdx.x;
    if (t < ETOT) {
        int src, dst;
        if (t < EE) { src = ei[t]; dst = ei[EE + t]; }
        else        { src = t - EE; dst = src; }
        int pos = g_offs[dst] + atomicAdd(&g_cur[dst], 1);
        g_srcs[pos] = src;
    }
}

// ---------------- weight pre-convert (tf32) ----------------
__global__ void split_w(const float* __restrict__ Wl, const float* __restrict__ Wr) {
    int i = blockIdx.x * blockDim.x + threadIdx.x;
    if (i >= 4 * 128 * 256) return;
    int layer = i >> 15;
    int rem = i & 32767;
    int k = rem >> 8;
    int c = rem & 255;
    float v = (c < 128) ? Wl[layer * 16384 + k * 128 + c]
                        : Wr[layer * 16384 + k * 128 + (c - 128)];
    g_WH[i] = f2tf32(v);
}

// ---------------- layer 0 GEMM (K=7) ----------------
__global__ void gemm0(const float* __restrict__ x,
                      const float* __restrict__ Wl0, const float* __restrict__ Wr0,
                      const float* __restrict__ bl0, const float* __restrict__ br0) {
    int node = blockIdx.x;
    int j = threadIdx.x;
    __shared__ float xs[7];
    if (j < 7) xs[j] = x[node * 7 + j];
    __syncthreads();
    const float* W = (j < 128) ? Wl0 : Wr0;
    int c = j & 127;
    float acc = (j < 128) ? bl0[c] : br0[c];
    #pragma unroll
    for (int k = 0; k < 7; k++) acc += xs[k] * W[k * 128 + c];
    if (j < 128) g_xl[node * DD + c] = acc;
    else         g_xr[node * DD + c] = acc;
}

// ---------------- TC GEMM: double-buffered, cp.async B, single tf32 MMA ----------------
#define KC 16
// per-stage words: As [128][20] = 2560 | BsH [16][136] = 2176
#define STAGE_WORDS 4736
#define OFF_BH 2560
#define GEMM_SMEM_BYTES (2 * STAGE_WORDS * 4)

__device__ __forceinline__ void mma_tf32(float c[4], const uint32_t a[4], uint32_t b0, uint32_t b1) {
    asm volatile(
        "mma.sync.aligned.m16n8k8.row.col.f32.tf32.tf32.f32 "
        "{%0,%1,%2,%3}, {%4,%5,%6,%7}, {%8,%9}, {%0,%1,%2,%3};"
        : "+f"(c[0]), "+f"(c[1]), "+f"(c[2]), "+f"(c[3])
        : "r"(a[0]), "r"(a[1]), "r"(a[2]), "r"(a[3]), "r"(b0), "r"(b1));
}

__device__ __forceinline__ void cp16(uint32_t* dst_smem, const uint32_t* src_gmem) {
    uint32_t saddr = (uint32_t)__cvta_generic_to_shared(dst_smem);
    asm volatile("cp.async.cg.shared.global [%0], [%1], 16;" :: "r"(saddr), "l"(src_gmem));
}

__global__ __launch_bounds__(256, 2) void gemm_tc(int layer,
                                                  const float* __restrict__ bl_,
                                                  const float* __restrict__ br_) {
    extern __shared__ uint32_t smem[];

    int tid  = threadIdx.x;
    int lane = tid & 31;
    int wid  = tid >> 5;
    int g    = lane >> 2;
    int tig  = lane & 3;
    int wm   = wid >> 1;
    int wn   = wid & 1;
    int m_base = wm * 32;
    int n_base = wn * 64;
    int row0 = blockIdx.x * 128;
    int yhalf = blockIdx.y;

    const uint32_t* WHbase = g_WH + layer * 32768 + yhalf * 128;

    float c[2][8][4];
    #pragma unroll
    for (int mi = 0; mi < 2; mi++)
        #pragma unroll
        for (int ni = 0; ni < 8; ni++)
            #pragma unroll
            for (int q = 0; q < 4; q++) c[mi][ni][q] = 0.f;

    int ar  = tid >> 1;
    int akq = (tid & 1) * 8;
    int bk  = tid >> 4;
    int bc  = (tid & 15) * 8;
    int arow = row0 + ar;
    bool a_ok = (arow < NN);
    const float* a_gp = &g_h[(size_t)arow * DD + akq];

    float4 fa0 = make_float4(0.f, 0.f, 0.f, 0.f);
    float4 fa1 = make_float4(0.f, 0.f, 0.f, 0.f);
    if (a_ok) {
        fa0 = *(const float4*)&a_gp[0];
        fa1 = *(const float4*)&a_gp[4];
    }
    {
        uint32_t* BH = smem + OFF_BH;
        const uint32_t* sH = WHbase + bk * 256 + bc;
        cp16(&BH[bk * 136 + bc],     &sH[0]);
        cp16(&BH[bk * 136 + bc + 4], &sH[4]);
        asm volatile("cp.async.commit_group;");
    }

    for (int it = 0; it < 8; it++) {
        int cur = it & 1;
        uint32_t* As  = smem + cur * STAGE_WORDS;
        uint32_t* BsH = As + OFF_BH;

        {
            float f[8] = {fmaxf(fa0.x, 0.f), fmaxf(fa0.y, 0.f), fmaxf(fa0.z, 0.f), fmaxf(fa0.w, 0.f),
                          fmaxf(fa1.x, 0.f), fmaxf(fa1.y, 0.f), fmaxf(fa1.z, 0.f), fmaxf(fa1.w, 0.f)};
            #pragma unroll
            for (int j = 0; j < 8; j++) As[ar * 20 + akq + j] = f2tf32(f[j]);
        }
        asm volatile("cp.async.wait_group 0;");
        __syncthreads();
        if (it < 7) {
            int k0n = (it + 1) * KC;
            if (a_ok) {
                fa0 = *(const float4*)&a_gp[k0n];
                fa1 = *(const float4*)&a_gp[k0n + 4];
            }
            uint32_t* An  = smem + ((it + 1) & 1) * STAGE_WORDS;
            uint32_t* BHn = An + OFF_BH;
            const uint32_t* sH = WHbase + (k0n + bk) * 256 + bc;
            cp16(&BHn[bk * 136 + bc],     &sH[0]);
            cp16(&BHn[bk * 136 + bc + 4], &sH[4]);
            asm volatile("cp.async.commit_group;");
        }

        #pragma unroll
        for (int ks = 0; ks < KC; ks += 8) {
            uint32_t a[2][4];
            #pragma unroll
            for (int mi = 0; mi < 2; mi++) {
                int r = m_base + mi * 16 + g;
                a[mi][0] = As[r * 20 + ks + tig];
                a[mi][1] = As[(r + 8) * 20 + ks + tig];
                a[mi][2] = As[r * 20 + ks + tig + 4];
                a[mi][3] = As[(r + 8) * 20 + ks + tig + 4];
            }
            #pragma unroll
            for (int ni = 0; ni < 8; ni++) {
                int cc = n_base + ni * 8 + g;
                uint32_t bH0 = BsH[(ks + tig) * 136 + cc];
                uint32_t bH1 = BsH[(ks + tig + 4) * 136 + cc];
                #pragma unroll
                for (int mi = 0; mi < 2; mi++)
                    mma_tf32(c[mi][ni], a[mi], bH0, bH1);
            }
        }
        __syncthreads();
    }

    // --- epilogue ---
    const float* bias = yhalf ? br_ : bl_;
    float* dst = yhalf ? g_xr : g_xl;
    #pragma unroll
    for (int ni = 0; ni < 8; ni++) {
        int cn = n_base + ni * 8 + tig * 2;
        float b0 = bias[cn], b1 = bias[cn + 1];
        #pragma unroll
        for (int mi = 0; mi < 2; mi++) {
            int ra = row0 + m_base + mi * 16 + g;
            int rb = ra + 8;
            if (ra < NN)
                *(float2*)&dst[ra * DD + cn] = make_float2(c[mi][ni][0] + b0, c[mi][ni][1] + b1);
            if (rb < NN)
                *(float2*)&dst[rb * DD + cn] = make_float2(c[mi][ni][2] + b0, c[mi][ni][3] + b1);
        }
    }
}

// ---------------- attention v4: warp per node, no-max softmax, ILP-4 + prefetch ----------------
__device__ __forceinline__ float dleaky(float4 c, float4 xr, float4 a, float d) {
    float v;
    v = c.x + xr.x; v = (v > 0.f) ? v : 0.2f * v; d = fmaf(v, a.x, d);
    v = c.y + xr.y; v = (v > 0.f) ? v : 0.2f * v; d = fmaf(v, a.y, d);
    v = c.z + xr.z; v = (v > 0.f) ? v : 0.2f * v; d = fmaf(v, a.z, d);
    v = c.w + xr.w; v = (v > 0.f) ? v : 0.2f * v; d = fmaf(v, a.w, d);
    return d;
}

__global__ void attn(const float* __restrict__ avec, const float* __restrict__ bvec,
                     float* __restrict__ outp) {
    const unsigned FULL = 0xffffffffu;
    int w = (blockIdx.x * blockDim.x + threadIdx.x) >> 5;
    if (w >= NN) return;
    int lane = threadIdx.x & 31;

    float4 xr4 = *(float4*)&g_xr[(size_t)w * DD + lane * 4];
    float4 a4  = *(const float4*)&avec[lane * 4];

    int p = g_offs[w], end = g_offs[w + 1];
    float s = 0.f;
    float ax = 0.f, ay = 0.f, az = 0.f, aw = 0.f;

    int p4end = p + ((end - p) & ~3);

    float4 c0, c1, c2, c3;
    if (p < p4end) {
        int s0 = g_srcs[p], s1 = g_srcs[p + 1], s2 = g_srcs[p + 2], s3 = g_srcs[p + 3];
        c0 = *(const float4*)&g_xl[(size_t)s0 * DD + lane * 4];
        c1 = *(const float4*)&g_xl[(size_t)s1 * DD + lane * 4];
        c2 = *(const float4*)&g_xl[(size_t)s2 * DD + lane * 4];
        c3 = *(const float4*)&g_xl[(size_t)s3 * DD + lane * 4];
    }

    while (p < p4end) {
        float4 u0 = c0, u1 = c1, u2 = c2, u3 = c3;
        int pn = p + 4;
        if (pn < p4end) {
            int s0 = g_srcs[pn], s1 = g_srcs[pn + 1], s2 = g_srcs[pn + 2], s3 = g_srcs[pn + 3];
            c0 = *(const float4*)&g_xl[(size_t)s0 * DD + lane * 4];
            c1 = *(const float4*)&g_xl[(size_t)s1 * DD + lane * 4];
            c2 = *(const float4*)&g_xl[(size_t)s2 * DD + lane * 4];
            c3 = *(const float4*)&g_xl[(size_t)s3 * DD + lane * 4];
        }

        float d0 = dleaky(u0, xr4, a4, 0.f);
        float d1 = dleaky(u1, xr4, a4, 0.f);
        float d2 = dleaky(u2, xr4, a4, 0.f);
        float d3 = dleaky(u3, xr4, a4, 0.f);

        #pragma unroll
        for (int off = 16; off >= 1; off >>= 1) {
            d0 += __shfl_xor_sync(FULL, d0, off);
            d1 += __shfl_xor_sync(FULL, d1, off);
            d2 += __shfl_xor_sync(FULL, d2, off);
            d3 += __shfl_xor_sync(FULL, d3, off);
        }

        float w0 = __expf(d0), w1 = __expf(d1), w2 = __expf(d2), w3 = __expf(d3);
        s += (w0 + w1) + (w2 + w3);
        ax += w0 * u0.x + w1 * u1.x + w2 * u2.x + w3 * u3.x;
        ay += w0 * u0.y + w1 * u1.y + w2 * u2.y + w3 * u3.y;
        az += w0 * u0.z + w1 * u1.z + w2 * u2.z + w3 * u3.z;
        aw += w0 * u0.w + w1 * u1.w + w2 * u2.w + w3 * u3.w;
        p = pn;
    }

    while (p < end) {
        int s0 = g_srcs[p];
        float4 u0 = *(const float4*)&g_xl[(size_t)s0 * DD + lane * 4];
        float d0 = dleaky(u0, xr4, a4, 0.f);
        #pragma unroll
        for (int off = 16; off >= 1; off >>= 1)
            d0 += __shfl_xor_sync(FULL, d0, off);
        float w0 = __expf(d0);
        s += w0;
        ax += w0 * u0.x;
        ay += w0 * u0.y;
        az += w0 * u0.z;
        aw += w0 * u0.w;
        p++;
    }

    float inv = 1.f / s;
    float4 b4 = *(const float4*)&bvec[lane * 4];
    float* o = outp ? outp : g_h;
    float4 r = make_float4(ax * inv + b4.x, ay * inv + b4.y,
                           az * inv + b4.z, aw * inv + b4.w);
    *(float4*)&o[(size_t)w * DD + lane * 4] = r;
}

// ---------------- launch ----------------
extern "C" void kernel_launch(void* const* d_in, const int* in_sizes, int n_in,
                              void* d_out, int out_size) {
    const float* x    = (const float*)d_in[0];
    const int*   ei   = (const int*)d_in[1];
    const float* Wl0  = (const float*)d_in[2];
    const float* Wr0  = (const float*)d_in[3];
    const float* bl0  = (const float*)d_in[4];
    const float* br0  = (const float*)d_in[5];
    const float* Wl   = (const float*)d_in[6];
    const float* Wr   = (const float*)d_in[7];
    const float* bl   = (const float*)d_in[8];
    const float* br   = (const float*)d_in[9];
    const float* att  = (const float*)d_in[10];
    const float* bias = (const float*)d_in[11];
    float* out = (float*)d_out;

    cudaFuncSetAttribute(gemm_tc, cudaFuncAttributeMaxDynamicSharedMemorySize, GEMM_SMEM_BYTES);

    zero_counts<<<(NN + 255) / 256, 256>>>();
    count_edges<<<(ETOT + 255) / 256, 256>>>(ei);
    scan_block<<<NBSCAN, 256>>>();
    scan_spine<<<1, 32>>>();
    scan_fix<<<(NN + 255) / 256, 256>>>();
    fill_edges<<<(ETOT + 255) / 256, 256>>>(ei);
    split_w<<<(4 * 128 * 256 + 255) / 256, 256>>>(Wl, Wr);

    const int attn_blocks = (NN * 32 + 255) / 256;
    dim3 tc_grid((NN + 127) / 128, 2);

    gemm0<<<NN, 256>>>(x, Wl0, Wr0, bl0, br0);
    attn<<<attn_blocks, 256>>>(att, bias, nullptr);

    for (int t = 1; t < 5; t++) {
        gemm_tc<<<tc_grid, 256, GEMM_SMEM_BYTES>>>(t - 1, bl + (size_t)(t - 1) * 128,
                                                   br + (size_t)(t - 1) * 128);
        attn<<<attn_blocks, 256>>>(att + (size_t)t * 128, bias + (size_t)t * 128,
                                   (t == 4) ? out : nullptr);
    }
}

// round 10
// speedup vs baseline: 1.2760x; 1.0299x over previous
#include <cuda_runtime.h>
#include <cstdint>

#define NN 50000
#define EE 800000
#define ETOT (EE + NN)
#define DD 128
#define NROWS_PAD 50048                 // 391*128, pad so gemm cp.async never reads past end
#define NBSCAN ((NN + 1023) / 1024)

// ---------------- static device scratch ----------------
__device__ uint32_t g_htf[NROWS_PAD * DD];   // tf32(relu(h)) — produced by attn, consumed by gemm A
__device__ float g_xl[NN * DD];
__device__ float g_xr[NN * DD];
__device__ int   g_deg[NN];
__device__ int   g_offs[NN + 1];
__device__ int   g_cur[NN];
__device__ int   g_srcs[ETOT];
__device__ int   g_bsums[NBSCAN];
// pre-converted tf32 weights: [layer][k][col 0..255 = Wl|Wr]
__device__ uint32_t g_WH[4 * 128 * 256];

__device__ __forceinline__ uint32_t f2tf32(float x) {
    uint32_t r;
    asm volatile("cvt.rna.tf32.f32 %0, %1;" : "=r"(r) : "f"(x));
    return r;
}

// ---------------- CSR build ----------------
__global__ void zero_counts() {
    int i = blockIdx.x * blockDim.x + threadIdx.x;
    if (i < NN) { g_deg[i] = 0; g_cur[i] = 0; }
}

__global__ void count_edges(const int* __restrict__ ei) {
    int t = blockIdx.x * blockDim.x + threadIdx.x;
    if (t < ETOT) {
        int dst = (t < EE) ? ei[EE + t] : (t - EE);
        atomicAdd(&g_deg[dst], 1);
    }
}

__global__ void scan_block() {
    __shared__ int sm[256];
    int t = threadIdx.x;
    int base = blockIdx.x * 1024 + t * 4;
    int v0 = (base + 0 < NN) ? g_deg[base + 0] : 0;
    int v1 = (base + 1 < NN) ? g_deg[base + 1] : 0;
    int v2 = (base + 2 < NN) ? g_deg[base + 2] : 0;
    int v3 = (base + 3 < NN) ? g_deg[base + 3] : 0;
    v1 += v0; v2 += v1; v3 += v2;
    sm[t] = v3;
    __syncthreads();
    #pragma unroll
    for (int off = 1; off < 256; off <<= 1) {
        int add = (t >= off) ? sm[t - off] : 0;
        __syncthreads();
        sm[t] += add;
        __syncthreads();
    }
    int prev = (t > 0) ? sm[t - 1] : 0;
    if (base + 0 < NN) g_offs[base + 0] = prev + v0;
    if (base + 1 < NN) g_offs[base + 1] = prev + v1;
    if (base + 2 < NN) g_offs[base + 2] = prev + v2;
    if (base + 3 < NN) g_offs[base + 3] = prev + v3;
    if (t == 255) g_bsums[blockIdx.x] = sm[255];
}

__global__ void scan_spine() {            // parallel exclusive scan over 49 block sums
    __shared__ int sm[64];
    int t = threadIdx.x;
    sm[t] = (t < NBSCAN) ? g_bsums[t] : 0;
    __syncthreads();
    #pragma unroll
    for (int off = 1; off < 64; off <<= 1) {
        int add = (t >= off) ? sm[t - off] : 0;
        __syncthreads();
        sm[t] += add;
        __syncthreads();
    }
    if (t < NBSCAN) g_bsums[t] = (t > 0) ? sm[t - 1] : 0;
}

__global__ void scan_fix() {
    int i = blockIdx.x * blockDim.x + threadIdx.x;
    if (i < NN) g_offs[i] = g_offs[i] - g_deg[i] + g_bsums[i >> 10];
    if (i == 0) g_offs[NN] = ETOT;
}

__global__ void fill_edges(const int* __restrict__ ei) {
    int t = blockIdx.x * blockDim.x + threadIdx.x;
    if (t < ETOT) {
        int src, dst;
        if (t < EE) { src = ei[t]; dst = ei[EE + t]; }
        else        { src = t - EE; dst = src; }
        int pos = g_offs[dst] + atomicAdd(&g_cur[dst], 1);
        g_srcs[pos] = src;
    }
}

// ---------------- weight pre-convert (tf32) ----------------
__global__ void split_w(const float* __restrict__ Wl, const float* __restrict__ Wr) {
    int i = blockIdx.x * blockDim.x + threadIdx.x;
    if (i >= 4 * 128 * 256) return;
    int layer = i >> 15;
    int rem = i & 32767;
    int k = rem >> 8;
    int c = rem & 255;
    float v = (c < 128) ? Wl[layer * 16384 + k * 128 + c]
                        : Wr[layer * 16384 + k * 128 + (c - 128)];
    g_WH[i] = f2tf32(v);
}

// ---------------- layer 0 GEMM (K=7) ----------------
__global__ void gemm0(const float* __restrict__ x,
                      const float* __restrict__ Wl0, const float* __restrict__ Wr0,
                      const float* __restrict__ bl0, const float* __restrict__ br0) {
    int node = blockIdx.x;
    int j = threadIdx.x;
    __shared__ float xs[7];
    if (j < 7) xs[j] = x[node * 7 + j];
    __syncthreads();
    const float* W = (j < 128) ? Wl0 : Wr0;
    int c = j & 127;
    float acc = (j < 128) ? bl0[c] : br0[c];
    #pragma unroll
    for (int k = 0; k < 7; k++) acc += xs[k] * W[k * 128 + c];
    if (j < 128) g_xl[node * DD + c] = acc;
    else         g_xr[node * DD + c] = acc;
}

// ---------------- TC GEMM: full cp.async staging (A pre-converted), single-barrier pipeline ----------------
#define KC 16
// per-stage words: As [128][20] = 2560 | BsH [16][136] = 2176
#define STAGE_WORDS 4736
#define OFF_BH 2560
#define GEMM_SMEM_BYTES (2 * STAGE_WORDS * 4)

__device__ __forceinline__ void mma_tf32(float c[4], const uint32_t a[4], uint32_t b0, uint32_t b1) {
    asm volatile(
        "mma.sync.aligned.m16n8k8.row.col.f32.tf32.tf32.f32 "
        "{%0,%1,%2,%3}, {%4,%5,%6,%7}, {%8,%9}, {%0,%1,%2,%3};"
        : "+f"(c[0]), "+f"(c[1]), "+f"(c[2]), "+f"(c[3])
        : "r"(a[0]), "r"(a[1]), "r"(a[2]), "r"(a[3]), "r"(b0), "r"(b1));
}

__device__ __forceinline__ void cp16(uint32_t* dst_smem, const uint32_t* src_gmem) {
    uint32_t saddr = (uint32_t)__cvta_generic_to_shared(dst_smem);
    asm volatile("cp.async.cg.shared.global [%0], [%1], 16;" :: "r"(saddr), "l"(src_gmem));
}

__global__ __launch_bounds__(256, 2) void gemm_tc(int layer,
                                                  const float* __restrict__ bl_,
                                                  const float* __restrict__ br_) {
    extern __shared__ uint32_t smem[];

    int tid  = threadIdx.x;
    int lane = tid & 31;
    int wid  = tid >> 5;
    int g    = lane >> 2;
    int tig  = lane & 3;
    int wm   = wid >> 1;
    int wn   = wid & 1;
    int m_base = wm * 32;
    int n_base = wn * 64;
    int row0 = blockIdx.x * 128;
    int yhalf = blockIdx.y;

    const uint32_t* WHbase = g_WH + layer * 32768 + yhalf * 128;

    float c[2][8][4];
    #pragma unroll
    for (int mi = 0; mi < 2; mi++)
        #pragma unroll
        for (int ni = 0; ni < 8; ni++)
            #pragma unroll
            for (int q = 0; q < 4; q++) c[mi][ni][q] = 0.f;

    int ar  = tid >> 1;                     // A: row 0..127
    int akq = (tid & 1) * 8;                // A: k offset (8 words)
    int bk  = tid >> 4;                     // B: k 0..15
    int bc  = (tid & 15) * 8;               // B: col offset (8 words)
    const uint32_t* a_gp = &g_htf[(size_t)(row0 + ar) * DD + akq];   // padded rows: always safe

    // prologue: stage 0
    {
        uint32_t* As = smem;
        uint32_t* BH = smem + OFF_BH;
        cp16(&As[ar * 20 + akq],     &a_gp[0]);
        cp16(&As[ar * 20 + akq + 4], &a_gp[4]);
        const uint32_t* sH = WHbase + bk * 256 + bc;
        cp16(&BH[bk * 136 + bc],     &sH[0]);
        cp16(&BH[bk * 136 + bc + 4], &sH[4]);
        asm volatile("cp.async.commit_group;");
    }

    for (int it = 0; it < 8; it++) {
        uint32_t* As  = smem + (it & 1) * STAGE_WORDS;
        uint32_t* BsH = As + OFF_BH;

        asm volatile("cp.async.wait_group 0;");
        __syncthreads();                    // stage(it) ready; compute(it-1) done in all threads

        if (it < 7) {                       // issue stage(it+1) into the other buffer
            int k0n = (it + 1) * KC;
            uint32_t* An  = smem + ((it + 1) & 1) * STAGE_WORDS;
            uint32_t* BHn = An + OFF_BH;
            cp16(&An[ar * 20 + akq],     &a_gp[k0n]);
            cp16(&An[ar * 20 + akq + 4], &a_gp[k0n + 4]);
            const uint32_t* sH = WHbase + (k0n + bk) * 256 + bc;
            cp16(&BHn[bk * 136 + bc],     &sH[0]);
            cp16(&BHn[bk * 136 + bc + 4], &sH[4]);
            asm volatile("cp.async.commit_group;");
        }

        #pragma unroll
        for (int ks = 0; ks < KC; ks += 8) {
            uint32_t a[2][4];
            #pragma unroll
            for (int mi = 0; mi < 2; mi++) {
                int r = m_base + mi * 16 + g;
                a[mi][0] = As[r * 20 + ks + tig];
                a[mi][1] = As[(r + 8) * 20 + ks + tig];
                a[mi][2] = As[r * 20 + ks + tig + 4];
                a[mi][3] = As[(r + 8) * 20 + ks + tig + 4];
            }
            #pragma unroll
            for (int ni = 0; ni < 8; ni++) {
                int cc = n_base + ni * 8 + g;
                uint32_t bH0 = BsH[(ks + tig) * 136 + cc];
                uint32_t bH1 = BsH[(ks + tig + 4) * 136 + cc];
                #pragma unroll
                for (int mi = 0; mi < 2; mi++)
                    mma_tf32(c[mi][ni], a[mi], bH0, bH1);
            }
        }
    }

    // --- epilogue ---
    const float* bias = yhalf ? br_ : bl_;
    float* dst = yhalf ? g_xr : g_xl;
    #pragma unroll
    for (int ni = 0; ni < 8; ni++) {
        int cn = n_base + ni * 8 + tig * 2;
        float b0 = bias[cn], b1 = bias[cn + 1];
        #pragma unroll
        for (int mi = 0; mi < 2; mi++) {
            int ra = row0 + m_base + mi * 16 + g;
            int rb = ra + 8;
            if (ra < NN)
                *(float2*)&dst[ra * DD + cn] = make_float2(c[mi][ni][0] + b0, c[mi][ni][1] + b1);
            if (rb < NN)
                *(float2*)&dst[rb * DD + cn] = make_float2(c[mi][ni][2] + b0, c[mi][ni][3] + b1);
        }
    }
}

// ---------------- attention: warp per node, no-max softmax, ILP-4 + prefetch ----------------
__device__ __forceinline__ float dleaky(float4 c, float4 xr, float4 a, float d) {
    float v;
    v = c.x + xr.x; v = (v > 0.f) ? v : 0.2f * v; d = fmaf(v, a.x, d);
    v = c.y + xr.y; v = (v > 0.f) ? v : 0.2f * v; d = fmaf(v, a.y, d);
    v = c.z + xr.z; v = (v > 0.f) ? v : 0.2f * v; d = fmaf(v, a.z, d);
    v = c.w + xr.w; v = (v > 0.f) ? v : 0.2f * v; d = fmaf(v, a.w, d);
    return d;
}

__global__ void attn(const float* __restrict__ avec, const float* __restrict__ bvec,
                     float* __restrict__ outp) {
    const unsigned FULL = 0xffffffffu;
    int w = (blockIdx.x * blockDim.x + threadIdx.x) >> 5;
    if (w >= NN) return;
    int lane = threadIdx.x & 31;

    float4 xr4 = *(float4*)&g_xr[(size_t)w * DD + lane * 4];
    float4 a4  = *(const float4*)&avec[lane * 4];

    int p = g_offs[w], end = g_offs[w + 1];
    float s = 0.f;
    float ax = 0.f, ay = 0.f, az = 0.f, aw = 0.f;

    int p4end = p + ((end - p) & ~3);

    float4 c0, c1, c2, c3;
    if (p < p4end) {
        int s0 = g_srcs[p], s1 = g_srcs[p + 1], s2 = g_srcs[p + 2], s3 = g_srcs[p + 3];
        c0 = *(const float4*)&g_xl[(size_t)s0 * DD + lane * 4];
        c1 = *(const float4*)&g_xl[(size_t)s1 * DD + lane * 4];
        c2 = *(const float4*)&g_xl[(size_t)s2 * DD + lane * 4];
        c3 = *(const float4*)&g_xl[(size_t)s3 * DD + lane * 4];
    }

    while (p < p4end) {
        float4 u0 = c0, u1 = c1, u2 = c2, u3 = c3;
        int pn = p + 4;
        if (pn < p4end) {
            int s0 = g_srcs[pn], s1 = g_srcs[pn + 1], s2 = g_srcs[pn + 2], s3 = g_srcs[pn + 3];
            c0 = *(const float4*)&g_xl[(size_t)s0 * DD + lane * 4];
            c1 = *(const float4*)&g_xl[(size_t)s1 * DD + lane * 4];
            c2 = *(const float4*)&g_xl[(size_t)s2 * DD + lane * 4];
            c3 = *(const float4*)&g_xl[(size_t)s3 * DD + lane * 4];
        }

        float d0 = dleaky(u0, xr4, a4, 0.f);
        float d1 = dleaky(u1, xr4, a4, 0.f);
        float d2 = dleaky(u2, xr4, a4, 0.f);
        float d3 = dleaky(u3, xr4, a4, 0.f);

        #pragma unroll
        for (int off = 16; off >= 1; off >>= 1) {
            d0 += __shfl_xor_sync(FULL, d0, off);
            d1 += __shfl_xor_sync(FULL, d1, off);
            d2 += __shfl_xor_sync(FULL, d2, off);
            d3 += __shfl_xor_sync(FULL, d3, off);
        }

        float w0 = __expf(d0), w1 = __expf(d1), w2 = __expf(d2), w3 = __expf(d3);
        s += (w0 + w1) + (w2 + w3);
        ax += w0 * u0.x + w1 * u1.x + w2 * u2.x + w3 * u3.x;
        ay += w0 * u0.y + w1 * u1.y + w2 * u2.y + w3 * u3.y;
        az += w0 * u0.z + w1 * u1.z + w2 * u2.z + w3 * u3.z;
        aw += w0 * u0.w + w1 * u1.w + w2 * u2.w + w3 * u3.w;
        p = pn;
    }

    while (p < end) {
        int s0 = g_srcs[p];
        float4 u0 = *(const float4*)&g_xl[(size_t)s0 * DD + lane * 4];
        float d0 = dleaky(u0, xr4, a4, 0.f);
        #pragma unroll
        for (int off = 16; off >= 1; off >>= 1)
            d0 += __shfl_xor_sync(FULL, d0, off);
        float w0 = __expf(d0);
        s += w0;
        ax += w0 * u0.x;
        ay += w0 * u0.y;
        az += w0 * u0.z;
        aw += w0 * u0.w;
        p++;
    }

    float inv = 1.f / s;
    float4 b4 = *(const float4*)&bvec[lane * 4];
    float4 r = make_float4(ax * inv + b4.x, ay * inv + b4.y,
                           az * inv + b4.z, aw * inv + b4.w);
    if (outp) {
        *(float4*)&outp[(size_t)w * DD + lane * 4] = r;
    } else {
        // produce tf32(relu(h)) for the next layer's GEMM A operand
        uint4 t;
        t.x = f2tf32(fmaxf(r.x, 0.f));
        t.y = f2tf32(fmaxf(r.y, 0.f));
        t.z = f2tf32(fmaxf(r.z, 0.f));
        t.w = f2tf32(fmaxf(r.w, 0.f));
        *(uint4*)&g_htf[(size_t)w * DD + lane * 4] = t;
    }
}

// ---------------- launch ----------------
extern "C" void kernel_launch(void* const* d_in, const int* in_sizes, int n_in,
                              void* d_out, int out_size) {
    const float* x    = (const float*)d_in[0];
    const int*   ei   = (const int*)d_in[1];
    const float* Wl0  = (const float*)d_in[2];
    const float* Wr0  = (const float*)d_in[3];
    const float* bl0  = (const float*)d_in[4];
    const float* br0  = (const float*)d_in[5];
    const float* Wl   = (const float*)d_in[6];
    const float* Wr   = (const float*)d_in[7];
    const float* bl   = (const float*)d_in[8];
    const float* br   = (const float*)d_in[9];
    const float* att  = (const float*)d_in[10];
    const float* bias = (const float*)d_in[11];
    float* out = (float*)d_out;

    cudaFuncSetAttribute(gemm_tc, cudaFuncAttributeMaxDynamicSharedMemorySize, GEMM_SMEM_BYTES);

    zero_counts<<<(NN + 255) / 256, 256>>>();
    count_edges<<<(ETOT + 255) / 256, 256>>>(ei);
    scan_block<<<NBSCAN, 256>>>();
    scan_spine<<<1, 64>>>();
    scan_fix<<<(NN + 255) / 256, 256>>>();
    fill_edges<<<(ETOT + 255) / 256, 256>>>(ei);
    split_w<<<(4 * 128 * 256 + 255) / 256, 256>>>(Wl, Wr);

    const int attn_blocks = (NN * 32 + 255) / 256;
    dim3 tc_grid((NN + 127) / 128, 2);

    gemm0<<<NN, 256>>>(x, Wl0, Wr0, bl0, br0);
    attn<<<attn_blocks, 256>>>(att, bias, nullptr);

    for (int t = 1; t < 5; t++) {
        gemm_tc<<<tc_grid, 256, GEMM_SMEM_BYTES>>>(t - 1, bl + (size_t)(t - 1) * 128,
                                                   br + (size_t)(t - 1) * 128);
        attn<<<attn_blocks, 256>>>(att + (size_t)t * 128, bias + (size_t)t * 128,
                                   (t == 4) ? out : nullptr);
    }
}